// round 3
// baseline (speedup 1.0000x reference)
#include <cuda_runtime.h>
#include <cuda_bf16.h>
#include <math_constants.h>

// Problem constants
#define B_DIM   32768
#define D_DIM   256
#define K_DIM   16
#define BD      (B_DIM * D_DIM)          // 8,388,608
#define BD4     (BD / 4)                 // 2,097,152 float4
#define NBLK    1184                     // 148 SMs * 8
#define NTHREADS 256

// Per-block partial sums for the deterministic loss reduction
__device__ float g_partials[2048];

__global__ __launch_bounds__(NTHREADS) void vq_main_kernel(
    const float* __restrict__ z,
    const float* __restrict__ codebooks,   // [D, K] row-major
    float* __restrict__ out)               // [BD zq][1 loss][BD idx]
{
    // Each thread owns 4 consecutive d values, invariant under grid-stride:
    // stride in float4 units = gridDim*blockDim (multiple of 64 = one row of float4s)
    const int lane_d = (threadIdx.x & 63) * 4;   // base d for this thread

    // Load this thread's 4x16 codebook slice into registers (16 x LDG.128)
    float cb[4][K_DIM];
    const float4* cb4 = reinterpret_cast<const float4*>(codebooks);
#pragma unroll
    for (int j = 0; j < 4; j++) {
#pragma unroll
        for (int q = 0; q < 4; q++) {
            float4 v = cb4[(lane_d + j) * 4 + q];
            cb[j][q * 4 + 0] = v.x;
            cb[j][q * 4 + 1] = v.y;
            cb[j][q * 4 + 2] = v.z;
            cb[j][q * 4 + 3] = v.w;
        }
    }

    const float4* z4   = reinterpret_cast<const float4*>(z);
    float4*       zq4  = reinterpret_cast<float4*>(out);
    float*        idxf = out + BD + 1;           // not 16B-aligned -> scalar stores

    float lsum = 0.0f;

    const long long stride = (long long)gridDim.x * NTHREADS;
    for (long long i = (long long)blockIdx.x * NTHREADS + threadIdx.x;
         i < BD4; i += stride)
    {
        float4 zv = z4[i];
        float zr[4] = {zv.x, zv.y, zv.z, zv.w};
        float qr[4];
        int   kr[4];

#pragma unroll
        for (int j = 0; j < 4; j++) {
            float zj = zr[j];
            float bestd = CUDART_INF_F;
            float bestv = cb[j][0];
            int   bestk = 0;
#pragma unroll
            for (int k = 0; k < K_DIM; k++) {
                float diff = zj - cb[j][k];
                float dist = diff * diff;
                // strict < keeps the FIRST minimum -> matches jnp.argmin ties
                if (dist < bestd) { bestd = dist; bestk = k; bestv = cb[j][k]; }
            }
            qr[j] = bestv;
            kr[j] = bestk;
            lsum += bestd;   // (z_q - z)^2 == bestd bit-exactly
        }

        float4 qv; qv.x = qr[0]; qv.y = qr[1]; qv.z = qr[2]; qv.w = qr[3];
        zq4[i] = qv;

        long long base = i * 4;
        idxf[base + 0] = (float)kr[0];
        idxf[base + 1] = (float)kr[1];
        idxf[base + 2] = (float)kr[2];
        idxf[base + 3] = (float)kr[3];
    }

    // Deterministic block reduction of lsum
    __shared__ float sred[NTHREADS / 32];
    // warp reduce
#pragma unroll
    for (int o = 16; o > 0; o >>= 1)
        lsum += __shfl_down_sync(0xFFFFFFFFu, lsum, o);
    if ((threadIdx.x & 31) == 0) sred[threadIdx.x >> 5] = lsum;
    __syncthreads();
    if (threadIdx.x < (NTHREADS / 32)) {
        float v = sred[threadIdx.x];
#pragma unroll
        for (int o = (NTHREADS / 64); o > 0; o >>= 1)
            v += __shfl_down_sync(0xFFFFFFFFu, v, o);
        if (threadIdx.x == 0) g_partials[blockIdx.x] = v;
    }
}

__global__ void vq_loss_kernel(float* __restrict__ out)
{
    __shared__ float sred[8];
    float v = 0.0f;
    for (int i = threadIdx.x; i < NBLK; i += 256) v += g_partials[i];
#pragma unroll
    for (int o = 16; o > 0; o >>= 1)
        v += __shfl_down_sync(0xFFFFFFFFu, v, o);
    if ((threadIdx.x & 31) == 0) sred[threadIdx.x >> 5] = v;
    __syncthreads();
    if (threadIdx.x < 8) {
        float t = sred[threadIdx.x];
#pragma unroll
        for (int o = 4; o > 0; o >>= 1)
            t += __shfl_down_sync(0xFFu, t, o);
        if (threadIdx.x == 0) {
            // vq_loss = (1 + commitment_cost) * sum / B
            out[BD] = t * (1.25f / (float)B_DIM);
        }
    }
}

extern "C" void kernel_launch(void* const* d_in, const int* in_sizes, int n_in,
                              void* d_out, int out_size)
{
    const float* z         = (const float*)d_in[0];
    const float* codebooks = (const float*)d_in[1];
    float*       out       = (float*)d_out;

    vq_main_kernel<<<NBLK, NTHREADS>>>(z, codebooks, out);
    vq_loss_kernel<<<1, 256>>>(out);
}

// round 9
// speedup vs baseline: 1.0067x; 1.0067x over previous
#include <cuda_runtime.h>
#include <cuda_bf16.h>

// Problem constants
#define B_DIM    32768
#define D_DIM    256
#define K_DIM    16
#define BD       (B_DIM * D_DIM)         // 8,388,608
#define BD4      (BD / 4)                // 2,097,152 float4
#define NBLK     1184                    // 148 SMs * 8
#define NTHREADS 256

__device__ float        g_partials[2048];
__device__ unsigned int g_count;          // zero-init; last block resets -> replay-safe

__global__ __launch_bounds__(NTHREADS) void vq_fused_kernel(
    const float* __restrict__ z,
    const float* __restrict__ codebooks,   // [D, K] row-major
    float* __restrict__ out)               // [BD zq][1 loss][BD idx]
{
    // Thread owns 4 consecutive d values; grid stride (multiple of 64 float4s
    // = one row) keeps the d-slice invariant across iterations.
    const int lane_d = (threadIdx.x & 63) * 4;

    // Register-resident codebook slice: 4 d's x 16 entries
    float cb[4][K_DIM];
    const float4* cb4 = reinterpret_cast<const float4*>(codebooks);
#pragma unroll
    for (int j = 0; j < 4; j++) {
#pragma unroll
        for (int q = 0; q < 4; q++) {
            float4 v = cb4[(lane_d + j) * 4 + q];
            cb[j][q * 4 + 0] = v.x;
            cb[j][q * 4 + 1] = v.y;
            cb[j][q * 4 + 2] = v.z;
            cb[j][q * 4 + 3] = v.w;
        }
    }

    const float4* z4  = reinterpret_cast<const float4*>(z);
    float4*       zq4 = reinterpret_cast<float4*>(out);
    float*        idxf = out + BD + 1;     // misaligned region -> scalar stores

    float lsum = 0.0f;
    const int stride = gridDim.x * NTHREADS;

    for (int i = blockIdx.x * NTHREADS + threadIdx.x; i < BD4; i += stride)
    {
        float4 zv = z4[i];
        float zr[4] = {zv.x, zv.y, zv.z, zv.w};
        float qr[4], kr[4];

#pragma unroll
        for (int j = 0; j < 4; j++) {
            const float zj = zr[j];

            // all 16 squared distances (independent -> full ILP)
            float d[K_DIM];
#pragma unroll
            for (int k = 0; k < K_DIM; k++) {
                float t = zj - cb[j][k];
                d[k] = t * t;
            }

            // tournament tree, depth 4. Right wins only on STRICT < at every
            // node => global first-minimum (matches jnp.argmin tie rule).
            float d8[8], v8[8], k8[8];
#pragma unroll
            for (int t = 0; t < 8; t++) {
                bool p = d[2*t+1] < d[2*t];
                d8[t] = p ? d[2*t+1] : d[2*t];
                v8[t] = p ? cb[j][2*t+1] : cb[j][2*t];
                k8[t] = p ? (float)(2*t+1) : (float)(2*t);
            }
            float d4[4], v4[4], k4[4];
#pragma unroll
            for (int t = 0; t < 4; t++) {
                bool p = d8[2*t+1] < d8[2*t];
                d4[t] = p ? d8[2*t+1] : d8[2*t];
                v4[t] = p ? v8[2*t+1] : v8[2*t];
                k4[t] = p ? k8[2*t+1] : k8[2*t];
            }
            float d2[2], v2[2], k2[2];
#pragma unroll
            for (int t = 0; t < 2; t++) {
                bool p = d4[2*t+1] < d4[2*t];
                d2[t] = p ? d4[2*t+1] : d4[2*t];
                v2[t] = p ? v4[2*t+1] : v4[2*t];
                k2[t] = p ? k4[2*t+1] : k4[2*t];
            }
            {
                bool p = d2[1] < d2[0];
                float bd = p ? d2[1] : d2[0];
                qr[j]    = p ? v2[1] : v2[0];
                kr[j]    = p ? k2[1] : k2[0];
                lsum += bd;                 // (z_q - z)^2 == bd bit-exactly
            }
        }

        float4 qv; qv.x = qr[0]; qv.y = qr[1]; qv.z = qr[2]; qv.w = qr[3];
        zq4[i] = qv;

        int base = i * 4;
        idxf[base + 0] = kr[0];
        idxf[base + 1] = kr[1];
        idxf[base + 2] = kr[2];
        idxf[base + 3] = kr[3];
    }

    // ---- deterministic block reduction of lsum ----
    __shared__ float sred[NTHREADS / 32];
    __shared__ bool  s_last;
#pragma unroll
    for (int o = 16; o > 0; o >>= 1)
        lsum += __shfl_down_sync(0xFFFFFFFFu, lsum, o);
    if ((threadIdx.x & 31) == 0) sred[threadIdx.x >> 5] = lsum;
    __syncthreads();
    if (threadIdx.x == 0) {
        float b = 0.0f;
#pragma unroll
        for (int w = 0; w < NTHREADS / 32; w++) b += sred[w];
        g_partials[blockIdx.x] = b;
        __threadfence();
        unsigned t = atomicAdd(&g_count, 1u);
        s_last = (t == gridDim.x - 1);
    }
    __syncthreads();

    // ---- last block: final deterministic reduction ----
    if (s_last) {
        float v = 0.0f;
        for (int p = threadIdx.x; p < NBLK; p += NTHREADS) v += g_partials[p];
#pragma unroll
        for (int o = 16; o > 0; o >>= 1)
            v += __shfl_down_sync(0xFFFFFFFFu, v, o);
        if ((threadIdx.x & 31) == 0) sred[threadIdx.x >> 5] = v;
        __syncthreads();
        if (threadIdx.x == 0) {
            float t = 0.0f;
#pragma unroll
            for (int w = 0; w < NTHREADS / 32; w++) t += sred[w];
            out[BD] = t * (1.25f / (float)B_DIM);   // (1+0.25) * sum / B
            g_count = 0;                             // reset for graph replay
        }
    }
}

extern "C" void kernel_launch(void* const* d_in, const int* in_sizes, int n_in,
                              void* d_out, int out_size)
{
    const float* z         = (const float*)d_in[0];
    const float* codebooks = (const float*)d_in[1];
    float*       out       = (float*)d_out;

    vq_fused_kernel<<<NBLK, NTHREADS>>>(z, codebooks, out);
}

// round 12
// speedup vs baseline: 1.2619x; 1.2535x over previous
#include <cuda_runtime.h>
#include <cuda_bf16.h>

// Problem constants
#define B_DIM    32768
#define D_DIM    256
#define K_DIM    16
#define BD       (B_DIM * D_DIM)         // 8,388,608
#define NBLK     1184                    // 148 SMs * 8
#define NTHREADS 256

__device__ float        g_partials[2048];
__device__ unsigned int g_count;          // zero-init; last block resets -> replay-safe

// 8-wide exact first-min tournament on (dist, value, index-as-float).
// Right wins only on STRICT < at every node => global first minimum.
__device__ __forceinline__ void argmin8(const float* d, const float* c, float kbase,
                                        float& bd, float& bv, float& bk)
{
    float d4[4], v4[4], k4[4];
#pragma unroll
    for (int t = 0; t < 4; t++) {
        bool p = d[2*t+1] < d[2*t];
        d4[t] = p ? d[2*t+1] : d[2*t];
        v4[t] = p ? c[2*t+1] : c[2*t];
        k4[t] = kbase + (p ? (float)(2*t+1) : (float)(2*t));
    }
    float d2[2], v2[2], k2[2];
#pragma unroll
    for (int t = 0; t < 2; t++) {
        bool p = d4[2*t+1] < d4[2*t];
        d2[t] = p ? d4[2*t+1] : d4[2*t];
        v2[t] = p ? v4[2*t+1] : v4[2*t];
        k2[t] = p ? k4[2*t+1] : k4[2*t];
    }
    bool p = d2[1] < d2[0];
    bd = p ? d2[1] : d2[0];
    bv = p ? v2[1] : v2[0];
    bk = p ? k2[1] : k2[0];
}

__global__ __launch_bounds__(NTHREADS, 4) void vq_fused_kernel(
    const float* __restrict__ z,
    const float* __restrict__ codebooks,   // [D, K] row-major
    float* __restrict__ out)               // [BD zq][1 loss][BD idx]
{
    const int tid = threadIdx.x;

    // One element per thread per iteration. Element index e has d = e % 256,
    // and since block offset and grid stride are multiples of 256, d == tid
    // for the whole lifetime of the thread -> codebook row in 16 registers.
    float cb[K_DIM];
    {
        const float4* cb4 = reinterpret_cast<const float4*>(codebooks) + tid * 4;
#pragma unroll
        for (int q = 0; q < 4; q++) {
            float4 v = cb4[q];
            cb[q*4+0] = v.x; cb[q*4+1] = v.y; cb[q*4+2] = v.z; cb[q*4+3] = v.w;
        }
    }

    float* __restrict__ idxf = out + BD + 1;
    float lsum = 0.0f;
    const int stride = NBLK * NTHREADS;     // multiple of 256

    for (int e = blockIdx.x * NTHREADS + tid; e < BD; e += stride)
    {
        const float zj = z[e];

        // first half: candidates 0..7
        float dA[8];
#pragma unroll
        for (int k = 0; k < 8; k++) { float t = zj - cb[k]; dA[k] = t * t; }
        float bdA, bvA, bkA;
        argmin8(dA, cb, 0.0f, bdA, bvA, bkA);

        // second half: candidates 8..15
        float dB[8];
#pragma unroll
        for (int k = 0; k < 8; k++) { float t = zj - cb[8 + k]; dB[k] = t * t; }
        float bdB, bvB, bkB;
        argmin8(dB, cb + 8, 8.0f, bdB, bvB, bkB);

        // merge (right wins only on strict <  => first minimum overall)
        bool p = bdB < bdA;
        float bd = p ? bdB : bdA;
        float bv = p ? bvB : bvA;
        float bk = p ? bkB : bkA;

        out[e]  = bv;      // coalesced STG.32
        idxf[e] = bk;      // coalesced STG.32 (+1 offset: 2 wavefronts)
        lsum += bd;        // (z_q - z)^2 == bd bit-exactly
    }

    // ---- deterministic block reduction of lsum ----
    __shared__ float sred[NTHREADS / 32];
    __shared__ bool  s_last;
#pragma unroll
    for (int o = 16; o > 0; o >>= 1)
        lsum += __shfl_down_sync(0xFFFFFFFFu, lsum, o);
    if ((tid & 31) == 0) sred[tid >> 5] = lsum;
    __syncthreads();
    if (tid == 0) {
        float b = 0.0f;
#pragma unroll
        for (int w = 0; w < NTHREADS / 32; w++) b += sred[w];
        g_partials[blockIdx.x] = b;
        __threadfence();
        unsigned t = atomicAdd(&g_count, 1u);
        s_last = (t == gridDim.x - 1);
    }
    __syncthreads();

    // ---- last block: final deterministic reduction ----
    if (s_last) {
        float v = 0.0f;
        for (int p = tid; p < NBLK; p += NTHREADS) v += g_partials[p];
#pragma unroll
        for (int o = 16; o > 0; o >>= 1)
            v += __shfl_down_sync(0xFFFFFFFFu, v, o);
        if ((tid & 31) == 0) sred[tid >> 5] = v;
        __syncthreads();
        if (tid == 0) {
            float t = 0.0f;
#pragma unroll
            for (int w = 0; w < NTHREADS / 32; w++) t += sred[w];
            out[BD] = t * (1.25f / (float)B_DIM);   // (1+0.25) * sum / B
            g_count = 0;                             // reset for graph replay
        }
    }
}

extern "C" void kernel_launch(void* const* d_in, const int* in_sizes, int n_in,
                              void* d_out, int out_size)
{
    const float* z         = (const float*)d_in[0];
    const float* codebooks = (const float*)d_in[1];
    float*       out       = (float*)d_out;

    vq_fused_kernel<<<NBLK, NTHREADS>>>(z, codebooks, out);
}